// round 10
// baseline (speedup 1.0000x reference)
#include <cuda_runtime.h>
#include <cstdint>

#define N_NODES 100000
#define N_EDGES 1600000
#define C 32
#define SLOTS 64   // P(Poisson(16) > 64) ~ 1e-20; guard keeps OOB-safe

// Scratch (device globals; zero-initialized at module load).
// g_cursor is reset to zero by k_gather each call -> replay-safe.
// g_elist slots beyond the live count may hold stale-but-valid node ids
// from earlier replays (inputs are identical every call) -> loads from the
// padded region are memory-safe; their values are masked out by predication.
__device__ int   g_cursor[N_NODES];
__device__ int   g_elist[N_NODES * SLOTS];     // 25.6 MB bin storage
__device__ float g_dinv[N_NODES];
__device__ float g_hs[N_NODES * C];            // hs[i] = (x[i] @ W^T) * dinv[i]

// ---------------------------------------------------------------------------
// K1: bin edges by target; cursor doubles as in-degree histogram.
__global__ void k_fill(const int* __restrict__ rowv,
                       const int* __restrict__ colv) {
    int e = blockIdx.x * blockDim.x + threadIdx.x;
    if (e < N_EDGES) {
        int c = __ldg(colv + e);
        int r = __ldg(rowv + e);
        int pos = atomicAdd(&g_cursor[c], 1);
        if (pos < SLOTS) g_elist[c * SLOTS + pos] = r;
    }
}

// K2: dinv = rsqrt(deg+1); hs = (x @ W^T) * dinv.
//     Reads g_cursor as degree (gather resets it). Block = 8 nodes x 32 ch.
__global__ void k_gemm(const float* __restrict__ x,
                       const float* __restrict__ W) {
    __shared__ float Wsh[C][C + 1];   // Wsh[k][co] = W[co*C + k]
    int tid = threadIdx.x;
    #pragma unroll
    for (int i = tid; i < C * C; i += 256) {
        Wsh[i % C][i / C] = W[i];
    }
    __syncthreads();

    int n  = blockIdx.x * 8 + (tid >> 5);
    int co = tid & 31;
    if (n >= N_NODES) return;

    float dinv = rsqrtf((float)(g_cursor[n] + 1));   // +1 = self loop
    if (co == 0) g_dinv[n] = dinv;

    const float* xr = x + n * C;
    float acc = 0.0f;
    #pragma unroll
    for (int k = 0; k < C; k++) acc += __ldg(xr + k) * Wsh[k][co];

    g_hs[n * C + co] = acc * dinv;
}

// K3: atomic-free gather. ONE WARP PER NODE, lane = channel.
//     Per 16-edge round: 4 broadcast int4 index loads, then 16 INDEPENDENT
//     perfectly-coalesced 128B hs loads (unconditional within the padded
//     bin), adds predicated on the live count -> MLP=16, no divergent chain.
//     out[n] = dinv[n]*(hs[n] + sum hs[src]) + b; resets cursor for replay.
__global__ void __launch_bounds__(256) k_gather(float* __restrict__ out,
                                                const float* __restrict__ b) {
    int n = blockIdx.x * 8 + (threadIdx.x >> 5);   // node id (warp per node)
    int co = threadIdx.x & 31;                     // channel
    if (n >= N_NODES) return;

    int deg = g_cursor[n];             // broadcast load
    if (co == 0) g_cursor[n] = 0;      // reset for next replay
    int cnt = min(deg, SLOTS);

    const int4* el4 = reinterpret_cast<const int4*>(g_elist + n * SLOTS);
    float acc = g_hs[n * C + co];      // self-loop term (coalesced 128B)

    for (int base = 0; base < cnt; base += 16) {
        int q = base >> 2;
        int4 a0 = __ldg(el4 + q);      // broadcast (1 sector each)
        int4 a1 = __ldg(el4 + q + 1);
        int4 a2 = __ldg(el4 + q + 2);
        int4 a3 = __ldg(el4 + q + 3);
        int idx[16] = {a0.x, a0.y, a0.z, a0.w, a1.x, a1.y, a1.z, a1.w,
                       a2.x, a2.y, a2.z, a2.w, a3.x, a3.y, a3.z, a3.w};
        float v[16];
        #pragma unroll
        for (int k = 0; k < 16; k++) {
            v[k] = __ldg(g_hs + idx[k] * C + co);   // 16 independent LDGs
        }
        #pragma unroll
        for (int k = 0; k < 16; k++) {
            if (base + k < cnt) acc += v[k];        // predicated adds
        }
    }

    out[n * C + co] = fmaf(acc, g_dinv[n], __ldg(b + co));
}

// ---------------------------------------------------------------------------
extern "C" void kernel_launch(void* const* d_in, const int* in_sizes, int n_in,
                              void* d_out, int out_size) {
    const float* x  = (const float*)d_in[0];
    const int*   ei = (const int*)d_in[1];    // [2, E]: row then col
    const float* W  = (const float*)d_in[2];
    const float* b  = (const float*)d_in[3];
    float* out = (float*)d_out;

    const int* rowv = ei;
    const int* colv = ei + N_EDGES;

    k_fill<<<(N_EDGES + 255) / 256, 256>>>(rowv, colv);
    k_gemm<<<(N_NODES + 7) / 8, 256>>>(x, W);
    k_gather<<<(N_NODES + 7) / 8, 256>>>(out, b);
}

// round 11
// speedup vs baseline: 1.8937x; 1.8937x over previous
#include <cuda_runtime.h>
#include <cstdint>

#define N_NODES 100000
#define N_EDGES 1600000
#define C 32

// Scratch (device globals; zero-initialized at module load).
// g_degi is consumed and re-zeroed by k_gemm each call -> replay-safe.
__device__ int    g_degi[N_NODES];
__device__ float  g_dinv[N_NODES];
__device__ float4 g_hs[N_NODES * (C / 4)];   // hs[i] = (x[i] @ W^T) * dinv[i]

// ---------------------------------------------------------------------------
// K1: in-degree histogram over targets, 1 edge/thread (proven ~12.7us).
__global__ void k_count(const int* __restrict__ col) {
    int e = blockIdx.x * blockDim.x + threadIdx.x;
    if (e < N_EDGES) atomicAdd(&g_degi[__ldg(col + e)], 1);
}

// K2: dinv = rsqrt(deg+1); hs = (x @ W^T) * dinv; out = hs (self-loop init).
//     Re-zeroes g_degi for the next replay. Block = 8 nodes x 32 channels.
__global__ void k_gemm(const float* __restrict__ x,
                       const float* __restrict__ W,
                       float* __restrict__ out) {
    __shared__ float Wsh[C][C + 1];   // Wsh[k][co] = W[co*C + k]
    int tid = threadIdx.x;
    #pragma unroll
    for (int i = tid; i < C * C; i += 256) {
        Wsh[i % C][i / C] = W[i];
    }
    __syncthreads();

    int n  = blockIdx.x * 8 + (tid >> 5);
    int co = tid & 31;
    if (n >= N_NODES) return;

    int deg = g_degi[n];
    if (co == 0) g_degi[n] = 0;                    // reset for next replay
    float dinv = rsqrtf((float)(deg + 1));         // +1 = self loop
    if (co == 0) g_dinv[n] = dinv;

    const float* xr = x + n * C;
    float acc = 0.0f;
    #pragma unroll
    for (int k = 0; k < C; k++) acc += __ldg(xr + k) * Wsh[k][co];

    float hs = acc * dinv;
    reinterpret_cast<float*>(g_hs)[n * C + co] = hs;
    out[n * C + co] = hs;   // self-loop accumulator init
}

// K3: bulk-reduce scatter — out[col*32..+32] += hs[row] via ONE
//     cp.reduce.async.bulk (128B) per edge, replacing 8 REDG lanes/edge.
//     8 lanes stage hs[row] into smem (coalesced LDG.128 + STS.128), then
//     lane g==0 of the group issues the bulk add. SM-side cost = 1 bulk
//     issue/edge instead of 8 REDG lanes/edge.
__global__ void __launch_bounds__(256) k_scatter_bulk(
        const int* __restrict__ rowv,
        const int* __restrict__ colv,
        float* __restrict__ out) {
    __shared__ float4 stage[32 * 8];   // 32 edges/block x 128B = 4KB

    int t  = blockIdx.x * 256 + threadIdx.x;
    int e  = t >> 3;                   // edge id
    int g  = t & 7;                    // lane within 8-lane group
    int le = threadIdx.x >> 3;         // local edge slot 0..31
    bool valid = (e < N_EDGES);

    int r = 0, c = 0;
    if (valid) {
        r = __ldg(rowv + e);
        c = __ldg(colv + e);
    }
    // stage hs[r] (128B) into this edge's smem slot
    stage[le * 8 + g] = g_hs[r * 8 + g];
    __syncwarp();
    asm volatile("fence.proxy.async.shared::cta;" ::: "memory");

    if (valid && g == 0) {
        uint32_t s = (uint32_t)__cvta_generic_to_shared(&stage[le * 8]);
        float* dst = out + (size_t)c * C;
        asm volatile(
            "cp.reduce.async.bulk.global.shared::cta.bulk_group.add.f32 "
            "[%0], [%1], %2;"
            :: "l"(dst), "r"(s), "r"(128) : "memory");
        asm volatile("cp.async.bulk.commit_group;" ::: "memory");
        // keep smem slot alive until the bulk read completes
        asm volatile("cp.async.bulk.wait_group 0;" ::: "memory");
    }
}

// K4: out = out * dinv[node] + b[channel], float4 per thread.
__global__ void k_final(float4* __restrict__ out, const float* __restrict__ b) {
    int i = blockIdx.x * blockDim.x + threadIdx.x;
    if (i < N_NODES * 8) {
        int n = i >> 3;
        int g = i & 7;
        float d = g_dinv[n];
        float4 v = out[i];
        float4 bb = *reinterpret_cast<const float4*>(b + g * 4);
        v.x = fmaf(v.x, d, bb.x);
        v.y = fmaf(v.y, d, bb.y);
        v.z = fmaf(v.z, d, bb.z);
        v.w = fmaf(v.w, d, bb.w);
        out[i] = v;
    }
}

// ---------------------------------------------------------------------------
extern "C" void kernel_launch(void* const* d_in, const int* in_sizes, int n_in,
                              void* d_out, int out_size) {
    const float* x  = (const float*)d_in[0];
    const int*   ei = (const int*)d_in[1];    // [2, E]: row then col
    const float* W  = (const float*)d_in[2];
    const float* b  = (const float*)d_in[3];
    float* out = (float*)d_out;

    const int* rowv = ei;
    const int* colv = ei + N_EDGES;

    k_count<<<(N_EDGES + 255) / 256, 256>>>(colv);
    k_gemm<<<(N_NODES + 7) / 8, 256>>>(x, W, out);
    k_scatter_bulk<<<(N_EDGES * 8 + 255) / 256, 256>>>(rowv, colv, out);
    k_final<<<(N_NODES * 8 + 511) / 512, 512>>>((float4*)out, b);
}